// round 1
// baseline (speedup 1.0000x reference)
#include <cuda_runtime.h>

#define B_ 8
#define T_ 2048
#define D_ 1024
#define SCALE_ 0.03125f   // 1/sqrt(1024)

// Scratch (sanctioned __device__ globals; no runtime allocation)
__device__ float g_S[(unsigned long long)B_ * T_ * T_];   // exp(masked logits), lower-tri valid
__device__ float g_C[(unsigned long long)B_ * T_ * D_];   // context
__device__ float g_den[B_ * T_];                          // softmax denominators

__device__ __forceinline__ float softplusf_(float v) {
    return v > 20.f ? v : log1pf(__expf(v));
}

__device__ __forceinline__ float gelu_tanh_(float v) {
    float u = 0.7978845608028654f * (v + 0.044715f * v * v * v);
    return 0.5f * v * (1.f + tanhf(u));
}

// ---------------------------------------------------------------------------
// Kernel 1: P = exp(SCALE * X X^T) with strict causal mask, lower-tri tiles only
// 128x128 tile, BK=16, 8x8 per thread, 256 threads
// ---------------------------------------------------------------------------
__global__ __launch_bounds__(256) void k_qk(const float* __restrict__ x) {
    const int sb = blockIdx.x;   // key block
    const int tb = blockIdx.y;   // query block
    const int b  = blockIdx.z;
    if (sb > tb) return;         // strictly-upper blocks fully masked: skip

    __shared__ float As[16][132];
    __shared__ float Bs[16][132];

    const float* X = x + (size_t)b * T_ * D_;
    const int tid = threadIdx.x;
    const int tr  = tid >> 4;          // 0..15
    const int tc  = tid & 15;          // 0..15
    const int lr  = tid >> 2;          // 0..63
    const int lc  = (tid & 3) << 2;    // 0,4,8,12
    const int t0 = tb * 128, s0 = sb * 128;

    float acc[8][8];
#pragma unroll
    for (int i = 0; i < 8; i++)
#pragma unroll
        for (int j = 0; j < 8; j++) acc[i][j] = 0.f;

    for (int kt = 0; kt < D_; kt += 16) {
#pragma unroll
        for (int r = 0; r < 2; r++) {
            float4 va = *(const float4*)(X + (size_t)(t0 + lr + r * 64) * D_ + kt + lc);
            As[lc + 0][lr + r * 64] = va.x;
            As[lc + 1][lr + r * 64] = va.y;
            As[lc + 2][lr + r * 64] = va.z;
            As[lc + 3][lr + r * 64] = va.w;
            float4 vb = *(const float4*)(X + (size_t)(s0 + lr + r * 64) * D_ + kt + lc);
            Bs[lc + 0][lr + r * 64] = vb.x;
            Bs[lc + 1][lr + r * 64] = vb.y;
            Bs[lc + 2][lr + r * 64] = vb.z;
            Bs[lc + 3][lr + r * 64] = vb.w;
        }
        __syncthreads();
#pragma unroll
        for (int kk = 0; kk < 16; kk++) {
            float ra[8], rb[8];
#pragma unroll
            for (int i = 0; i < 8; i++) ra[i] = As[kk][tr * 8 + i];
#pragma unroll
            for (int j = 0; j < 8; j++) rb[j] = Bs[kk][tc * 8 + j];
#pragma unroll
            for (int i = 0; i < 8; i++)
#pragma unroll
                for (int j = 0; j < 8; j++) acc[i][j] = fmaf(ra[i], rb[j], acc[i][j]);
        }
        __syncthreads();
    }

    float* Sb = g_S + (size_t)b * T_ * T_;
#pragma unroll
    for (int i = 0; i < 8; i++) {
        const int t = t0 + tr * 8 + i;
        const size_t base = (size_t)t * T_ + s0 + tc * 8;
#pragma unroll
        for (int jj = 0; jj < 2; jj++) {
            const int s = s0 + tc * 8 + jj * 4;
            float4 v;
            v.x = (s + 0 < t) ? __expf(acc[i][jj * 4 + 0] * SCALE_) : 0.f;
            v.y = (s + 1 < t) ? __expf(acc[i][jj * 4 + 1] * SCALE_) : 0.f;
            v.z = (s + 2 < t) ? __expf(acc[i][jj * 4 + 2] * SCALE_) : 0.f;
            v.w = (s + 3 < t) ? __expf(acc[i][jj * 4 + 3] * SCALE_) : 0.f;
            *(float4*)(Sb + base + jj * 4) = v;
        }
    }
}

// ---------------------------------------------------------------------------
// Kernel 2: denominators. One warp per (b,t) row, deterministic sum over s<t.
// ---------------------------------------------------------------------------
__global__ __launch_bounds__(256) void k_denom() {
    const int warp = (blockIdx.x * 256 + threadIdx.x) >> 5;
    const int lane = threadIdx.x & 31;
    if (warp >= B_ * T_) return;
    const int b = warp / T_, t = warp % T_;
    const float* row = g_S + ((size_t)b * T_ + t) * T_;
    float s = 0.f;
    for (int j = lane; j < t; j += 32) s += row[j];
#pragma unroll
    for (int o = 16; o; o >>= 1) s += __shfl_down_sync(0xFFFFFFFFu, s, o);
    if (lane == 0) g_den[warp] = s;
}

// ---------------------------------------------------------------------------
// Kernel 3: context = (P @ X) / denom. K truncated at (tb+1)*128 (lower-tri).
// ---------------------------------------------------------------------------
__global__ __launch_bounds__(256) void k_av(const float* __restrict__ x) {
    const int nb = blockIdx.x;   // d block (0..7)
    const int tb = blockIdx.y;   // t block (0..15)
    const int b  = blockIdx.z;

    __shared__ float As[16][132];
    __shared__ float Bs[16][128];

    const float* Sb = g_S + (size_t)b * T_ * T_;
    const float* X  = x  + (size_t)b * T_ * D_;
    const int tid = threadIdx.x;
    const int tr  = tid >> 4, tc = tid & 15;
    const int lrA = tid >> 2,  lcA = (tid & 3) << 2;
    const int lrB = tid >> 5,  lcB = (tid & 31) << 2;
    const int t0 = tb * 128, d0 = nb * 128;
    const int Kmax = (tb + 1) * 128;

    float acc[8][8];
#pragma unroll
    for (int i = 0; i < 8; i++)
#pragma unroll
        for (int j = 0; j < 8; j++) acc[i][j] = 0.f;

    for (int kt = 0; kt < Kmax; kt += 16) {
#pragma unroll
        for (int r = 0; r < 2; r++) {
            float4 va = *(const float4*)(Sb + (size_t)(t0 + lrA + r * 64) * T_ + kt + lcA);
            As[lcA + 0][lrA + r * 64] = va.x;
            As[lcA + 1][lrA + r * 64] = va.y;
            As[lcA + 2][lrA + r * 64] = va.z;
            As[lcA + 3][lrA + r * 64] = va.w;
            float4 vb = *(const float4*)(X + (size_t)(kt + lrB + r * 8) * D_ + d0 + lcB);
            *(float4*)&Bs[lrB + r * 8][lcB] = vb;
        }
        __syncthreads();
#pragma unroll
        for (int kk = 0; kk < 16; kk++) {
            float ra[8], rb[8];
#pragma unroll
            for (int i = 0; i < 8; i++) ra[i] = As[kk][tr * 8 + i];
#pragma unroll
            for (int j = 0; j < 8; j++) rb[j] = Bs[kk][tc * 8 + j];
#pragma unroll
            for (int i = 0; i < 8; i++)
#pragma unroll
                for (int j = 0; j < 8; j++) acc[i][j] = fmaf(ra[i], rb[j], acc[i][j]);
        }
        __syncthreads();
    }

#pragma unroll
    for (int i = 0; i < 8; i++) {
        const int t = t0 + tr * 8 + i;
        const float den = g_den[b * T_ + t];
        const float inv = den > 0.f ? 1.f / den : 0.f;
        const size_t base = ((size_t)b * T_ + t) * D_ + d0 + tc * 8;
        float4 v0, v1;
        v0.x = acc[i][0] * inv; v0.y = acc[i][1] * inv;
        v0.z = acc[i][2] * inv; v0.w = acc[i][3] * inv;
        v1.x = acc[i][4] * inv; v1.y = acc[i][5] * inv;
        v1.z = acc[i][6] * inv; v1.w = acc[i][7] * inv;
        *(float4*)(g_C + base)     = v0;
        *(float4*)(g_C + base + 4) = v1;
    }
}

// ---------------------------------------------------------------------------
// Kernel 4: cosine / novelty / gate / tanh-GELU. One CTA per (b,t) row.
// ---------------------------------------------------------------------------
__global__ __launch_bounds__(256) void k_epi(const float* __restrict__ x,
                                             const float* __restrict__ p_la,
                                             const float* __restrict__ p_ls,
                                             float* __restrict__ out) {
    const int row = blockIdx.x;          // b*T + t
    const int tid = threadIdx.x;
    const float4 xv = *((const float4*)x   + (size_t)row * 256 + tid);
    const float4 cv = *((const float4*)g_C + (size_t)row * 256 + tid);

    float xx = xv.x * xv.x + xv.y * xv.y + xv.z * xv.z + xv.w * xv.w;
    float cc = cv.x * cv.x + cv.y * cv.y + cv.z * cv.z + cv.w * cv.w;
    float xc = xv.x * cv.x + xv.y * cv.y + xv.z * cv.z + xv.w * cv.w;

#pragma unroll
    for (int o = 16; o; o >>= 1) {
        xx += __shfl_down_sync(0xFFFFFFFFu, xx, o);
        cc += __shfl_down_sync(0xFFFFFFFFu, cc, o);
        xc += __shfl_down_sync(0xFFFFFFFFu, xc, o);
    }

    __shared__ float s_xx[8], s_cc[8], s_xc[8];
    __shared__ float s_gate;
    const int lane = tid & 31, w = tid >> 5;
    if (lane == 0) { s_xx[w] = xx; s_cc[w] = cc; s_xc[w] = xc; }
    __syncthreads();
    if (tid == 0) {
        float fxx = 0.f, fcc = 0.f, fxc = 0.f;
#pragma unroll
        for (int k = 0; k < 8; k++) { fxx += s_xx[k]; fcc += s_cc[k]; fxc += s_xc[k]; }
        const float nx = fmaxf(sqrtf(fxx), 1e-12f);
        const float nc = fmaxf(sqrtf(fcc), 1e-12f);
        const float cosv = fxc / (nx * nc);
        const float nov  = fminf(fmaxf(1.f - cosv, 0.f), 2.f) * 0.5f;
        const float alpha = softplusf_(*p_la);
        const float sigma = softplusf_(*p_ls);
        s_gate = 1.f + alpha * tanhf(sigma * nov);
    }
    __syncthreads();
    const float g = s_gate;

    float4 o;
    o.x = gelu_tanh_(xv.x * g);
    o.y = gelu_tanh_(xv.y * g);
    o.z = gelu_tanh_(xv.z * g);
    o.w = gelu_tanh_(xv.w * g);
    *((float4*)out + (size_t)row * 256 + tid) = o;
}

// ---------------------------------------------------------------------------
extern "C" void kernel_launch(void* const* d_in, const int* in_sizes, int n_in,
                              void* d_out, int out_size) {
    const float* x  = (const float*)d_in[0];
    const float* la = (const float*)d_in[1];
    const float* ls = (const float*)d_in[2];
    float* out = (float*)d_out;

    dim3 g1(16, 16, 8);
    k_qk<<<g1, 256>>>(x);

    k_denom<<<(B_ * T_) / 8, 256>>>();

    dim3 g3(8, 16, 8);
    k_av<<<g3, 256>>>(x);

    k_epi<<<B_ * T_, 256>>>(x, la, ls, out);
}

// round 3
// speedup vs baseline: 4.6896x; 4.6896x over previous
#include <cuda_runtime.h>
#include <cuda_bf16.h>
#include <stdint.h>

#define B_ 8
#define T_ 2048
#define D_ 1024
#define SCALE_ 0.03125f   // 1/sqrt(1024)

// ---------------------------------------------------------------------------
// Scratch (__device__ globals; no runtime allocation)
// ---------------------------------------------------------------------------
__device__ __nv_bfloat16 g_Xh [(size_t)B_ * T_ * D_];   // x in bf16, [b,t,d]
__device__ __nv_bfloat16 g_XhT[(size_t)B_ * D_ * T_];   // x^T in bf16, [b,d,t]
__device__ __nv_bfloat16 g_Sh [(size_t)B_ * T_ * T_];   // exp(masked logits), bf16
__device__ float         g_C  [(size_t)B_ * T_ * D_];   // context (fp32)
__device__ float         g_den[B_ * T_];                // softmax denominators

// ---------------------------------------------------------------------------
// Helpers (baseline PTX only — must assemble for compute_100 without 'a')
// ---------------------------------------------------------------------------
__device__ __forceinline__ uint32_t smem_u32(const void* p) {
    uint32_t a;
    asm("{ .reg .u64 t; cvta.to.shared.u64 t, %1; cvt.u32.u64 %0, t; }"
        : "=r"(a) : "l"(p));
    return a;
}

__device__ __forceinline__ void cp16(uint32_t dst, const void* src) {
    asm volatile("cp.async.cg.shared.global [%0], [%1], 16;"
                 :: "r"(dst), "l"(src) : "memory");
}
#define CP_COMMIT() asm volatile("cp.async.commit_group;" ::: "memory")
#define CP_WAIT(N)  asm volatile("cp.async.wait_group %0;" :: "n"(N) : "memory")

__device__ __forceinline__ void ldmx4(uint32_t& r0, uint32_t& r1,
                                      uint32_t& r2, uint32_t& r3, uint32_t addr) {
    asm volatile("ldmatrix.sync.aligned.m8n8.x4.shared.b16 {%0,%1,%2,%3}, [%4];"
                 : "=r"(r0), "=r"(r1), "=r"(r2), "=r"(r3) : "r"(addr));
}

__device__ __forceinline__ void mma16816(float* c, const uint32_t* a,
                                         uint32_t b0, uint32_t b1) {
    asm volatile(
        "mma.sync.aligned.m16n8k16.row.col.f32.bf16.bf16.f32 "
        "{%0,%1,%2,%3}, {%4,%5,%6,%7}, {%8,%9}, {%0,%1,%2,%3};"
        : "+f"(c[0]), "+f"(c[1]), "+f"(c[2]), "+f"(c[3])
        : "r"(a[0]), "r"(a[1]), "r"(a[2]), "r"(a[3]), "r"(b0), "r"(b1));
}

__device__ __forceinline__ uint32_t sw128(uint32_t off) {
    return off ^ ((off >> 3) & 0x70);
}

__device__ __forceinline__ float softplusf_(float v) {
    return v > 20.f ? v : log1pf(__expf(v));
}
__device__ __forceinline__ float gelu_tanh_(float v) {
    float u = 0.7978845608028654f * (v + 0.044715f * v * v * v);
    return 0.5f * v * (1.f + tanhf(u));
}

// ---------------------------------------------------------------------------
// Kernel 0: convert x -> bf16 (row-major and transposed)
// ---------------------------------------------------------------------------
__global__ __launch_bounds__(256) void k_cvt(const float* __restrict__ x) {
    __shared__ __nv_bfloat16 tile[32][34];
    const int b  = blockIdx.z;
    const int t0 = blockIdx.x * 32;
    const int d0 = blockIdx.y * 32;
    const int lx = threadIdx.x;   // 0..15
    const int ly = threadIdx.y;   // 0..15
    const float* X = x + (size_t)b * T_ * D_;

#pragma unroll
    for (int r = 0; r < 2; r++) {
        const int t = t0 + ly + r * 16;
        const int d = d0 + lx * 2;
        float2 v = *(const float2*)(X + (size_t)t * D_ + d);
        __nv_bfloat162 h = __floats2bfloat162_rn(v.x, v.y);
        *(uint32_t*)(g_Xh + (size_t)(b * T_ + t) * D_ + d) = *(uint32_t*)&h;
        tile[ly + r * 16][lx * 2 + 0] = h.x;
        tile[ly + r * 16][lx * 2 + 1] = h.y;
    }
    __syncthreads();
#pragma unroll
    for (int r = 0; r < 2; r++) {
        const int d  = d0 + ly + r * 16;
        const int tp = lx * 2;
        __nv_bfloat162 h;
        h.x = tile[tp + 0][ly + r * 16];
        h.y = tile[tp + 1][ly + r * 16];
        *(uint32_t*)(g_XhT + ((size_t)b * D_ + d) * T_ + t0 + tp) = *(uint32_t*)&h;
    }
}

// ---------------------------------------------------------------------------
// Core MMA tile compute: 128x128 CTA tile, 8 warps (2m x 4n), K-chunk 64.
// A tile at smem sA (128 rows x 128B), B tile at sB. Both K-major SW128.
// Accumulates into c[4][4][4].
// ---------------------------------------------------------------------------
__device__ __forceinline__ void mma_chunk(uint32_t sA, uint32_t sB,
                                          int warp_m, int warp_n, int lane,
                                          float c[4][4][4]) {
    const int rowsel = lane & 15;
    const int khalf  = lane >> 4;
#pragma unroll
    for (int ks = 0; ks < 4; ks++) {
        const uint32_t kbyte = ks * 32 + khalf * 16;
        uint32_t a[4][4];
#pragma unroll
        for (int mi = 0; mi < 4; mi++) {
            const uint32_t row = warp_m * 64 + mi * 16 + rowsel;
            ldmx4(a[mi][0], a[mi][1], a[mi][2], a[mi][3],
                  sA + sw128(row * 128 + kbyte));
        }
        uint32_t b[4][2];
#pragma unroll
        for (int nj = 0; nj < 2; nj++) {
            const uint32_t nrow = warp_n * 32 + nj * 16 + rowsel;
            uint32_t r0, r1, r2, r3;
            ldmx4(r0, r1, r2, r3, sB + sw128(nrow * 128 + kbyte));
            b[nj * 2 + 0][0] = r0; b[nj * 2 + 1][0] = r1;
            b[nj * 2 + 0][1] = r2; b[nj * 2 + 1][1] = r3;
        }
#pragma unroll
        for (int mi = 0; mi < 4; mi++)
#pragma unroll
            for (int ni = 0; ni < 4; ni++)
                mma16816(c[mi][ni], a[mi], b[ni][0], b[ni][1]);
    }
}

// Async load of one 128x(64 bf16) tile stage: 256 threads, 4 cp16 each.
__device__ __forceinline__ void load_tile(uint32_t sdst,
                                          const __nv_bfloat16* __restrict__ src,
                                          size_t row_stride, int tid) {
    const int row  = tid >> 1;
    const int cbase = (tid & 1) * 4;
    const __nv_bfloat16* g = src + (size_t)row * row_stride + cbase * 8;
#pragma unroll
    for (int c = 0; c < 4; c++)
        cp16(sdst + sw128(row * 128 + (cbase + c) * 16), g + c * 8);
}

// ---------------------------------------------------------------------------
// Kernel 1: S = exp(SCALE * X X^T) bf16, strict causal, lower-tri CTAs only
// ---------------------------------------------------------------------------
__global__ __launch_bounds__(256) void k_qk_mma() {
    const int sb = blockIdx.x, tb = blockIdx.y, b = blockIdx.z;
    if (sb > tb) return;

    extern __shared__ __align__(1024) char smem[];
    const uint32_t sbase = smem_u32(smem);
    const int tid = threadIdx.x, lane = tid & 31, wid = tid >> 5;
    const int warp_m = wid & 1, warp_n = wid >> 1;

    const __nv_bfloat16* A0 = g_Xh + (size_t)(b * T_ + tb * 128) * D_;
    const __nv_bfloat16* B0 = g_Xh + (size_t)(b * T_ + sb * 128) * D_;

    float c[4][4][4];
#pragma unroll
    for (int mi = 0; mi < 4; mi++)
#pragma unroll
        for (int ni = 0; ni < 4; ni++)
#pragma unroll
            for (int k = 0; k < 4; k++) c[mi][ni][k] = 0.f;

    // preload stage 0
    load_tile(sbase,         A0, D_, tid);
    load_tile(sbase + 16384, B0, D_, tid);
    CP_COMMIT();

    const int nIter = D_ / 64;   // 16
    for (int it = 0; it < nIter; ++it) {
        if (it + 1 < nIter) {
            const uint32_t stb = sbase + ((it + 1) & 1) * 32768;
            const int kt = (it + 1) * 64;
            load_tile(stb,         A0 + kt, D_, tid);
            load_tile(stb + 16384, B0 + kt, D_, tid);
            CP_COMMIT();
            CP_WAIT(1);
        } else {
            CP_WAIT(0);
        }
        __syncthreads();
        const uint32_t st = sbase + (it & 1) * 32768;
        mma_chunk(st, st + 16384, warp_m, warp_n, lane, c);
        __syncthreads();
    }

    // epilogue: exp + strict mask, bf16 store
    const int quad = lane >> 2, qid = lane & 3;
#pragma unroll
    for (int mi = 0; mi < 4; mi++) {
#pragma unroll
        for (int ni = 0; ni < 4; ni++) {
            const int col = warp_n * 32 + ni * 8 + qid * 2;
            const int s0  = sb * 128 + col;
#pragma unroll
            for (int h = 0; h < 2; h++) {
                const int row = warp_m * 64 + mi * 16 + quad + h * 8;
                const int t   = tb * 128 + row;
                float v0 = (s0 + 0 < t) ? __expf(c[mi][ni][2 * h + 0] * SCALE_) : 0.f;
                float v1 = (s0 + 1 < t) ? __expf(c[mi][ni][2 * h + 1] * SCALE_) : 0.f;
                __nv_bfloat162 hv = __floats2bfloat162_rn(v0, v1);
                *(uint32_t*)(g_Sh + ((size_t)(b * T_ + t)) * T_ + s0) = *(uint32_t*)&hv;
            }
        }
    }
}

// ---------------------------------------------------------------------------
// Kernel 2: denominators. One warp per (b,t) row (masked entries are zeros).
// ---------------------------------------------------------------------------
__global__ __launch_bounds__(256) void k_denom() {
    const int warp = (blockIdx.x * 256 + threadIdx.x) >> 5;
    const int lane = threadIdx.x & 31;
    if (warp >= B_ * T_) return;
    const int b = warp / T_, t = warp % T_;
    const int Kmax = ((t >> 7) + 1) << 7;
    const __nv_bfloat162* row2 =
        (const __nv_bfloat162*)(g_Sh + ((size_t)b * T_ + t) * T_);
    float s = 0.f;
    const int np = Kmax >> 1;
    for (int j = lane; j < np; j += 32) {
        float2 f = __bfloat1622float2(row2[j]);
        s += f.x + f.y;
    }
#pragma unroll
    for (int o = 16; o; o >>= 1) s += __shfl_down_sync(0xFFFFFFFFu, s, o);
    if (lane == 0) g_den[warp] = s;
}

// ---------------------------------------------------------------------------
// Kernel 3: context = (S @ X) / den. A = S rows, B = X^T rows. K to diag.
// ---------------------------------------------------------------------------
__global__ __launch_bounds__(256) void k_av_mma() {
    const int nb = blockIdx.x, tb = blockIdx.y, b = blockIdx.z;

    extern __shared__ __align__(1024) char smem[];
    const uint32_t sbase = smem_u32(smem);
    const int tid = threadIdx.x, lane = tid & 31, wid = tid >> 5;
    const int warp_m = wid & 1, warp_n = wid >> 1;

    const __nv_bfloat16* A0 = g_Sh  + (size_t)(b * T_ + tb * 128) * T_;
    const __nv_bfloat16* B0 = g_XhT + ((size_t)b * D_ + nb * 128) * T_;

    float c[4][4][4];
#pragma unroll
    for (int mi = 0; mi < 4; mi++)
#pragma unroll
        for (int ni = 0; ni < 4; ni++)
#pragma unroll
            for (int k = 0; k < 4; k++) c[mi][ni][k] = 0.f;

    load_tile(sbase,         A0, T_, tid);
    load_tile(sbase + 16384, B0, T_, tid);
    CP_COMMIT();

    const int nIter = (tb + 1) * 2;   // K = (tb+1)*128 in chunks of 64
    for (int it = 0; it < nIter; ++it) {
        if (it + 1 < nIter) {
            const uint32_t stb = sbase + ((it + 1) & 1) * 32768;
            const int kt = (it + 1) * 64;
            load_tile(stb,         A0 + kt, T_, tid);
            load_tile(stb + 16384, B0 + kt, T_, tid);
            CP_COMMIT();
            CP_WAIT(1);
        } else {
            CP_WAIT(0);
        }
        __syncthreads();
        const uint32_t st = sbase + (it & 1) * 32768;
        mma_chunk(st, st + 16384, warp_m, warp_n, lane, c);
        __syncthreads();
    }

    // epilogue: divide by denom, fp32 store
    const int quad = lane >> 2, qid = lane & 3;
#pragma unroll
    for (int mi = 0; mi < 4; mi++) {
#pragma unroll
        for (int h = 0; h < 2; h++) {
            const int row = warp_m * 64 + mi * 16 + quad + h * 8;
            const int t   = tb * 128 + row;
            const float den = g_den[b * T_ + t];
            const float inv = den > 0.f ? 1.f / den : 0.f;
            float* crow = g_C + ((size_t)(b * T_ + t)) * D_ + nb * 128;
#pragma unroll
            for (int ni = 0; ni < 4; ni++) {
                const int col = warp_n * 32 + ni * 8 + qid * 2;
                float2 v;
                v.x = c[mi][ni][2 * h + 0] * inv;
                v.y = c[mi][ni][2 * h + 1] * inv;
                *(float2*)(crow + col) = v;
            }
        }
    }
}

// ---------------------------------------------------------------------------
// Kernel 4: cosine / novelty / gate / tanh-GELU. One CTA per (b,t) row.
// ---------------------------------------------------------------------------
__global__ __launch_bounds__(256) void k_epi(const float* __restrict__ x,
                                             const float* __restrict__ p_la,
                                             const float* __restrict__ p_ls,
                                             float* __restrict__ out) {
    const int row = blockIdx.x;
    const int tid = threadIdx.x;
    const float4 xv = *((const float4*)x   + (size_t)row * 256 + tid);
    const float4 cv = *((const float4*)g_C + (size_t)row * 256 + tid);

    float xx = xv.x * xv.x + xv.y * xv.y + xv.z * xv.z + xv.w * xv.w;
    float cc = cv.x * cv.x + cv.y * cv.y + cv.z * cv.z + cv.w * cv.w;
    float xc = xv.x * cv.x + xv.y * cv.y + xv.z * cv.z + xv.w * cv.w;

#pragma unroll
    for (int o = 16; o; o >>= 1) {
        xx += __shfl_down_sync(0xFFFFFFFFu, xx, o);
        cc += __shfl_down_sync(0xFFFFFFFFu, cc, o);
        xc += __shfl_down_sync(0xFFFFFFFFu, xc, o);
    }

    __shared__ float s_xx[8], s_cc[8], s_xc[8];
    __shared__ float s_gate;
    const int lane = tid & 31, w = tid >> 5;
    if (lane == 0) { s_xx[w] = xx; s_cc[w] = cc; s_xc[w] = xc; }
    __syncthreads();
    if (tid == 0) {
        float fxx = 0.f, fcc = 0.f, fxc = 0.f;
#pragma unroll
        for (int k = 0; k < 8; k++) { fxx += s_xx[k]; fcc += s_cc[k]; fxc += s_xc[k]; }
        const float nx = fmaxf(sqrtf(fxx), 1e-12f);
        const float nc = fmaxf(sqrtf(fcc), 1e-12f);
        const float cosv = fxc / (nx * nc);
        const float nov  = fminf(fmaxf(1.f - cosv, 0.f), 2.f) * 0.5f;
        const float alpha = softplusf_(*p_la);
        const float sigma = softplusf_(*p_ls);
        s_gate = 1.f + alpha * tanhf(sigma * nov);
    }
    __syncthreads();
    const float g = s_gate;

    float4 o;
    o.x = gelu_tanh_(xv.x * g);
    o.y = gelu_tanh_(xv.y * g);
    o.z = gelu_tanh_(xv.z * g);
    o.w = gelu_tanh_(xv.w * g);
    *((float4*)out + (size_t)row * 256 + tid) = o;
}

// ---------------------------------------------------------------------------
extern "C" void kernel_launch(void* const* d_in, const int* in_sizes, int n_in,
                              void* d_out, int out_size) {
    const float* x  = (const float*)d_in[0];
    const float* la = (const float*)d_in[1];
    const float* ls = (const float*)d_in[2];
    float* out = (float*)d_out;

    cudaFuncSetAttribute(k_qk_mma, cudaFuncAttributeMaxDynamicSharedMemorySize, 65536);
    cudaFuncSetAttribute(k_av_mma, cudaFuncAttributeMaxDynamicSharedMemorySize, 65536);

    dim3 gc(T_ / 32, D_ / 32, B_);
    k_cvt<<<gc, dim3(16, 16)>>>(x);

    dim3 g1(16, 16, B_);
    k_qk_mma<<<g1, 256, 65536>>>();

    k_denom<<<(B_ * T_) / 8, 256>>>();

    dim3 g3(8, 16, B_);
    k_av_mma<<<g3, 256, 65536>>>();

    k_epi<<<B_ * T_, 256>>>(x, la, ls, out);
}

// round 4
// speedup vs baseline: 4.8739x; 1.0393x over previous
#include <cuda_runtime.h>
#include <cuda_bf16.h>
#include <stdint.h>

#define B_ 8
#define T_ 2048
#define D_ 1024
#define SCALE_ 0.03125f   // 1/sqrt(1024)

#define NSTAGE 3
#define STAGE_BYTES 32768

// ---------------------------------------------------------------------------
// Scratch (__device__ globals; no runtime allocation)
// ---------------------------------------------------------------------------
__device__ __nv_bfloat16 g_Xh [(size_t)B_ * T_ * D_];   // x in bf16, [b,t,d]
__device__ __nv_bfloat16 g_XhT[(size_t)B_ * D_ * T_];   // x^T in bf16, [b,d,t]
__device__ __nv_bfloat16 g_Sh [(size_t)B_ * T_ * T_];   // exp(masked logits), bf16
__device__ float         g_C  [(size_t)B_ * T_ * D_];   // context (fp32)
__device__ float         g_den[B_ * T_];                // softmax denominators

// ---------------------------------------------------------------------------
// Helpers (baseline PTX only — must assemble for compute_100 without 'a')
// ---------------------------------------------------------------------------
__device__ __forceinline__ uint32_t smem_u32(const void* p) {
    uint32_t a;
    asm("{ .reg .u64 t; cvta.to.shared.u64 t, %1; cvt.u32.u64 %0, t; }"
        : "=r"(a) : "l"(p));
    return a;
}

__device__ __forceinline__ void cp16(uint32_t dst, const void* src) {
    asm volatile("cp.async.cg.shared.global [%0], [%1], 16;"
                 :: "r"(dst), "l"(src) : "memory");
}
#define CP_COMMIT() asm volatile("cp.async.commit_group;" ::: "memory")
#define CP_WAIT(N)  asm volatile("cp.async.wait_group %0;" :: "n"(N) : "memory")

__device__ __forceinline__ void ldmx4(uint32_t& r0, uint32_t& r1,
                                      uint32_t& r2, uint32_t& r3, uint32_t addr) {
    asm volatile("ldmatrix.sync.aligned.m8n8.x4.shared.b16 {%0,%1,%2,%3}, [%4];"
                 : "=r"(r0), "=r"(r1), "=r"(r2), "=r"(r3) : "r"(addr));
}

__device__ __forceinline__ void mma16816(float* c, const uint32_t* a,
                                         uint32_t b0, uint32_t b1) {
    asm volatile(
        "mma.sync.aligned.m16n8k16.row.col.f32.bf16.bf16.f32 "
        "{%0,%1,%2,%3}, {%4,%5,%6,%7}, {%8,%9}, {%0,%1,%2,%3};"
        : "+f"(c[0]), "+f"(c[1]), "+f"(c[2]), "+f"(c[3])
        : "r"(a[0]), "r"(a[1]), "r"(a[2]), "r"(a[3]), "r"(b0), "r"(b1));
}

__device__ __forceinline__ uint32_t sw128(uint32_t off) {
    return off ^ ((off >> 3) & 0x70);
}

__device__ __forceinline__ float softplusf_(float v) {
    return v > 20.f ? v : log1pf(__expf(v));
}
__device__ __forceinline__ float gelu_tanh_(float v) {
    float u = 0.7978845608028654f * (v + 0.044715f * v * v * v);
    return 0.5f * v * (1.f + tanhf(u));
}

// ---------------------------------------------------------------------------
// Kernel 0: convert x -> bf16 (row-major and transposed)
// ---------------------------------------------------------------------------
__global__ __launch_bounds__(256) void k_cvt(const float* __restrict__ x) {
    __shared__ __nv_bfloat16 tile[32][34];
    const int b  = blockIdx.z;
    const int t0 = blockIdx.x * 32;
    const int d0 = blockIdx.y * 32;
    const int lx = threadIdx.x;   // 0..15
    const int ly = threadIdx.y;   // 0..15
    const float* X = x + (size_t)b * T_ * D_;

#pragma unroll
    for (int r = 0; r < 2; r++) {
        const int t = t0 + ly + r * 16;
        const int d = d0 + lx * 2;
        float2 v = *(const float2*)(X + (size_t)t * D_ + d);
        __nv_bfloat162 h = __floats2bfloat162_rn(v.x, v.y);
        *(uint32_t*)(g_Xh + (size_t)(b * T_ + t) * D_ + d) = *(uint32_t*)&h;
        tile[ly + r * 16][lx * 2 + 0] = h.x;
        tile[ly + r * 16][lx * 2 + 1] = h.y;
    }
    __syncthreads();
#pragma unroll
    for (int r = 0; r < 2; r++) {
        const int d  = d0 + ly + r * 16;
        const int tp = lx * 2;
        __nv_bfloat162 h;
        h.x = tile[tp + 0][ly + r * 16];
        h.y = tile[tp + 1][ly + r * 16];
        *(uint32_t*)(g_XhT + ((size_t)b * D_ + d) * T_ + t0 + tp) = *(uint32_t*)&h;
    }
}

// ---------------------------------------------------------------------------
// Core MMA tile compute: 128x128 CTA tile, 8 warps (2m x 4n), K-chunk 64.
// ---------------------------------------------------------------------------
__device__ __forceinline__ void mma_chunk(uint32_t sA, uint32_t sB,
                                          int warp_m, int warp_n, int lane,
                                          float c[4][4][4]) {
    const int rowsel = lane & 15;
    const int khalf  = lane >> 4;
#pragma unroll
    for (int ks = 0; ks < 4; ks++) {
        const uint32_t kbyte = ks * 32 + khalf * 16;
        uint32_t a[4][4];
#pragma unroll
        for (int mi = 0; mi < 4; mi++) {
            const uint32_t row = warp_m * 64 + mi * 16 + rowsel;
            ldmx4(a[mi][0], a[mi][1], a[mi][2], a[mi][3],
                  sA + sw128(row * 128 + kbyte));
        }
        uint32_t b[4][2];
#pragma unroll
        for (int nj = 0; nj < 2; nj++) {
            const uint32_t nrow = warp_n * 32 + nj * 16 + rowsel;
            uint32_t r0, r1, r2, r3;
            ldmx4(r0, r1, r2, r3, sB + sw128(nrow * 128 + kbyte));
            b[nj * 2 + 0][0] = r0; b[nj * 2 + 1][0] = r1;
            b[nj * 2 + 0][1] = r2; b[nj * 2 + 1][1] = r3;
        }
#pragma unroll
        for (int mi = 0; mi < 4; mi++)
#pragma unroll
            for (int ni = 0; ni < 4; ni++)
                mma16816(c[mi][ni], a[mi], b[ni][0], b[ni][1]);
    }
}

// Async load of one 128x(64 bf16) tile stage: 256 threads, 4 cp16 each.
__device__ __forceinline__ void load_tile(uint32_t sdst,
                                          const __nv_bfloat16* __restrict__ src,
                                          size_t row_stride, int tid) {
    const int row  = tid >> 1;
    const int cbase = (tid & 1) * 4;
    const __nv_bfloat16* g = src + (size_t)row * row_stride + cbase * 8;
#pragma unroll
    for (int c = 0; c < 4; c++)
        cp16(sdst + sw128(row * 128 + (cbase + c) * 16), g + c * 8);
}

// ---------------------------------------------------------------------------
// Kernel 1: S = exp(SCALE * X X^T) bf16, strict causal. Triangular launch.
// ---------------------------------------------------------------------------
__global__ __launch_bounds__(256) void k_qk_mma() {
    // decode lower-triangular tile index (136 tiles: 0 <= sb <= tb <= 15)
    const int idx = blockIdx.x;
    int tb = (int)((sqrtf(8.f * (float)idx + 1.f) - 1.f) * 0.5f);
    while ((tb + 1) * (tb + 2) / 2 <= idx) tb++;
    while (tb * (tb + 1) / 2 > idx) tb--;
    const int sb = idx - tb * (tb + 1) / 2;
    const int b  = blockIdx.y;

    extern __shared__ __align__(1024) char smem[];
    const uint32_t sbase = smem_u32(smem);
    const int tid = threadIdx.x, lane = tid & 31, wid = tid >> 5;
    const int warp_m = wid & 1, warp_n = wid >> 1;

    const __nv_bfloat16* A0 = g_Xh + (size_t)(b * T_ + tb * 128) * D_;
    const __nv_bfloat16* B0 = g_Xh + (size_t)(b * T_ + sb * 128) * D_;

    float c[4][4][4];
#pragma unroll
    for (int mi = 0; mi < 4; mi++)
#pragma unroll
        for (int ni = 0; ni < 4; ni++)
#pragma unroll
            for (int k = 0; k < 4; k++) c[mi][ni][k] = 0.f;

    const int nIter = D_ / 64;   // 16
    // prologue: stages 0..NSTAGE-2
#pragma unroll
    for (int s = 0; s < NSTAGE - 1; s++) {
        const uint32_t st = sbase + s * STAGE_BYTES;
        load_tile(st,         A0 + s * 64, D_, tid);
        load_tile(st + 16384, B0 + s * 64, D_, tid);
        CP_COMMIT();
    }

    for (int it = 0; it < nIter; ++it) {
        if (it + NSTAGE - 1 < nIter) CP_WAIT(NSTAGE - 2); else CP_WAIT(0);
        __syncthreads();
        if (it + NSTAGE - 1 < nIter) {
            const int ld = it + NSTAGE - 1;
            const uint32_t stb = sbase + (ld % NSTAGE) * STAGE_BYTES;
            load_tile(stb,         A0 + ld * 64, D_, tid);
            load_tile(stb + 16384, B0 + ld * 64, D_, tid);
            CP_COMMIT();
        }
        const uint32_t st = sbase + (it % NSTAGE) * STAGE_BYTES;
        mma_chunk(st, st + 16384, warp_m, warp_n, lane, c);
    }

    // epilogue: exp + strict mask, bf16 store
    const int quad = lane >> 2, qid = lane & 3;
#pragma unroll
    for (int mi = 0; mi < 4; mi++) {
#pragma unroll
        for (int ni = 0; ni < 4; ni++) {
            const int col = warp_n * 32 + ni * 8 + qid * 2;
            const int s0  = sb * 128 + col;
#pragma unroll
            for (int h = 0; h < 2; h++) {
                const int row = warp_m * 64 + mi * 16 + quad + h * 8;
                const int t   = tb * 128 + row;
                float v0 = (s0 + 0 < t) ? __expf(c[mi][ni][2 * h + 0] * SCALE_) : 0.f;
                float v1 = (s0 + 1 < t) ? __expf(c[mi][ni][2 * h + 1] * SCALE_) : 0.f;
                __nv_bfloat162 hv = __floats2bfloat162_rn(v0, v1);
                *(uint32_t*)(g_Sh + ((size_t)(b * T_ + t)) * T_ + s0) = *(uint32_t*)&hv;
            }
        }
    }
}

// ---------------------------------------------------------------------------
// Kernel 2: denominators. One warp per (b,t) row (masked entries are zeros).
// ---------------------------------------------------------------------------
__global__ __launch_bounds__(256) void k_denom() {
    const int warp = (blockIdx.x * 256 + threadIdx.x) >> 5;
    const int lane = threadIdx.x & 31;
    if (warp >= B_ * T_) return;
    const int b = warp / T_, t = warp % T_;
    const int Kmax = ((t >> 7) + 1) << 7;
    const __nv_bfloat162* row2 =
        (const __nv_bfloat162*)(g_Sh + ((size_t)b * T_ + t) * T_);
    float s = 0.f;
    const int np = Kmax >> 1;
    for (int j = lane; j < np; j += 32) {
        float2 f = __bfloat1622float2(row2[j]);
        s += f.x + f.y;
    }
#pragma unroll
    for (int o = 16; o; o >>= 1) s += __shfl_down_sync(0xFFFFFFFFu, s, o);
    if (lane == 0) g_den[warp] = s;
}

// ---------------------------------------------------------------------------
// Kernel 3: context = (S @ X) / den. Heavy tiles (large tb) launch first.
// ---------------------------------------------------------------------------
__global__ __launch_bounds__(256) void k_av_mma() {
    const int nb = blockIdx.x;
    const int tb = (int)gridDim.y - 1 - (int)blockIdx.y;   // heavy-first
    const int b  = blockIdx.z;

    extern __shared__ __align__(1024) char smem[];
    const uint32_t sbase = smem_u32(smem);
    const int tid = threadIdx.x, lane = tid & 31, wid = tid >> 5;
    const int warp_m = wid & 1, warp_n = wid >> 1;

    const __nv_bfloat16* A0 = g_Sh  + (size_t)(b * T_ + tb * 128) * T_;
    const __nv_bfloat16* B0 = g_XhT + ((size_t)b * D_ + nb * 128) * T_;

    float c[4][4][4];
#pragma unroll
    for (int mi = 0; mi < 4; mi++)
#pragma unroll
        for (int ni = 0; ni < 4; ni++)
#pragma unroll
            for (int k = 0; k < 4; k++) c[mi][ni][k] = 0.f;

    const int nIter = (tb + 1) * 2;   // K = (tb+1)*128 in chunks of 64
#pragma unroll
    for (int s = 0; s < NSTAGE - 1; s++) {
        if (s < nIter) {
            const uint32_t st = sbase + s * STAGE_BYTES;
            load_tile(st,         A0 + s * 64, T_, tid);
            load_tile(st + 16384, B0 + s * 64, T_, tid);
            CP_COMMIT();
        }
    }

    for (int it = 0; it < nIter; ++it) {
        if (it + NSTAGE - 1 < nIter) CP_WAIT(NSTAGE - 2); else CP_WAIT(0);
        __syncthreads();
        if (it + NSTAGE - 1 < nIter) {
            const int ld = it + NSTAGE - 1;
            const uint32_t stb = sbase + (ld % NSTAGE) * STAGE_BYTES;
            load_tile(stb,         A0 + ld * 64, T_, tid);
            load_tile(stb + 16384, B0 + ld * 64, T_, tid);
            CP_COMMIT();
        }
        const uint32_t st = sbase + (it % NSTAGE) * STAGE_BYTES;
        mma_chunk(st, st + 16384, warp_m, warp_n, lane, c);
    }

    // epilogue: divide by denom, fp32 store
    const int quad = lane >> 2, qid = lane & 3;
#pragma unroll
    for (int mi = 0; mi < 4; mi++) {
#pragma unroll
        for (int h = 0; h < 2; h++) {
            const int row = warp_m * 64 + mi * 16 + quad + h * 8;
            const int t   = tb * 128 + row;
            const float den = g_den[b * T_ + t];
            const float inv = den > 0.f ? 1.f / den : 0.f;
            float* crow = g_C + ((size_t)(b * T_ + t)) * D_ + nb * 128;
#pragma unroll
            for (int ni = 0; ni < 4; ni++) {
                const int col = warp_n * 32 + ni * 8 + qid * 2;
                float2 v;
                v.x = c[mi][ni][2 * h + 0] * inv;
                v.y = c[mi][ni][2 * h + 1] * inv;
                *(float2*)(crow + col) = v;
            }
        }
    }
}

// ---------------------------------------------------------------------------
// Kernel 4: cosine / novelty / gate / tanh-GELU. One CTA per (b,t) row.
// ---------------------------------------------------------------------------
__global__ __launch_bounds__(256) void k_epi(const float* __restrict__ x,
                                             const float* __restrict__ p_la,
                                             const float* __restrict__ p_ls,
                                             float* __restrict__ out) {
    const int row = blockIdx.x;
    const int tid = threadIdx.x;
    const float4 xv = *((const float4*)x   + (size_t)row * 256 + tid);
    const float4 cv = *((const float4*)g_C + (size_t)row * 256 + tid);

    float xx = xv.x * xv.x + xv.y * xv.y + xv.z * xv.z + xv.w * xv.w;
    float cc = cv.x * cv.x + cv.y * cv.y + cv.z * cv.z + cv.w * cv.w;
    float xc = xv.x * cv.x + xv.y * cv.y + xv.z * cv.z + xv.w * cv.w;

#pragma unroll
    for (int o = 16; o; o >>= 1) {
        xx += __shfl_down_sync(0xFFFFFFFFu, xx, o);
        cc += __shfl_down_sync(0xFFFFFFFFu, cc, o);
        xc += __shfl_down_sync(0xFFFFFFFFu, xc, o);
    }

    __shared__ float s_xx[8], s_cc[8], s_xc[8];
    __shared__ float s_gate;
    const int lane = tid & 31, w = tid >> 5;
    if (lane == 0) { s_xx[w] = xx; s_cc[w] = cc; s_xc[w] = xc; }
    __syncthreads();
    if (tid == 0) {
        float fxx = 0.f, fcc = 0.f, fxc = 0.f;
#pragma unroll
        for (int k = 0; k < 8; k++) { fxx += s_xx[k]; fcc += s_cc[k]; fxc += s_xc[k]; }
        const float nx = fmaxf(sqrtf(fxx), 1e-12f);
        const float nc = fmaxf(sqrtf(fcc), 1e-12f);
        const float cosv = fxc / (nx * nc);
        const float nov  = fminf(fmaxf(1.f - cosv, 0.f), 2.f) * 0.5f;
        const float alpha = softplusf_(*p_la);
        const float sigma = softplusf_(*p_ls);
        s_gate = 1.f + alpha * tanhf(sigma * nov);
    }
    __syncthreads();
    const float g = s_gate;

    float4 o;
    o.x = gelu_tanh_(xv.x * g);
    o.y = gelu_tanh_(xv.y * g);
    o.z = gelu_tanh_(xv.z * g);
    o.w = gelu_tanh_(xv.w * g);
    *((float4*)out + (size_t)row * 256 + tid) = o;
}

// ---------------------------------------------------------------------------
extern "C" void kernel_launch(void* const* d_in, const int* in_sizes, int n_in,
                              void* d_out, int out_size) {
    const float* x  = (const float*)d_in[0];
    const float* la = (const float*)d_in[1];
    const float* ls = (const float*)d_in[2];
    float* out = (float*)d_out;

    const int smem_bytes = NSTAGE * STAGE_BYTES;
    cudaFuncSetAttribute(k_qk_mma, cudaFuncAttributeMaxDynamicSharedMemorySize, smem_bytes);
    cudaFuncSetAttribute(k_av_mma, cudaFuncAttributeMaxDynamicSharedMemorySize, smem_bytes);

    dim3 gc(T_ / 32, D_ / 32, B_);
    k_cvt<<<gc, dim3(16, 16)>>>(x);

    dim3 g1(136, B_);
    k_qk_mma<<<g1, 256, smem_bytes>>>();

    k_denom<<<(B_ * T_) / 8, 256>>>();

    dim3 g3(8, 16, B_);
    k_av_mma<<<g3, 256, smem_bytes>>>();

    k_epi<<<B_ * T_, 256>>>(x, la, ls, out);
}

// round 5
// speedup vs baseline: 4.8995x; 1.0053x over previous
#include <cuda_runtime.h>
#include <cuda_bf16.h>
#include <stdint.h>

#define B_ 8
#define T_ 2048
#define D_ 1024
#define SCALE_ 0.03125f   // 1/sqrt(1024)

#define NSTAGE 3
#define A_BYTES 8192        // 64 rows x 128B
#define B_BYTES 16384       // 128 rows x 128B
#define STAGE_BYTES (A_BYTES + B_BYTES)   // 24576

// ---------------------------------------------------------------------------
// Scratch (__device__ globals; no runtime allocation)
// ---------------------------------------------------------------------------
__device__ __nv_bfloat16 g_Xh [(size_t)B_ * T_ * D_];   // x in bf16, [b,t,d]
__device__ __nv_bfloat16 g_XhT[(size_t)B_ * D_ * T_];   // x^T in bf16, [b,d,t]
__device__ __nv_bfloat16 g_Sh [(size_t)B_ * T_ * T_];   // exp(masked logits), bf16
__device__ float         g_C  [(size_t)B_ * T_ * D_];   // context (fp32)
__device__ float         g_den[B_ * T_];                // softmax denominators

// ---------------------------------------------------------------------------
// Helpers (baseline PTX only)
// ---------------------------------------------------------------------------
__device__ __forceinline__ uint32_t smem_u32(const void* p) {
    uint32_t a;
    asm("{ .reg .u64 t; cvta.to.shared.u64 t, %1; cvt.u32.u64 %0, t; }"
        : "=r"(a) : "l"(p));
    return a;
}

__device__ __forceinline__ void cp16(uint32_t dst, const void* src) {
    asm volatile("cp.async.cg.shared.global [%0], [%1], 16;"
                 :: "r"(dst), "l"(src) : "memory");
}
#define CP_COMMIT() asm volatile("cp.async.commit_group;" ::: "memory")
#define CP_WAIT(N)  asm volatile("cp.async.wait_group %0;" :: "n"(N) : "memory")

__device__ __forceinline__ void ldmx4(uint32_t& r0, uint32_t& r1,
                                      uint32_t& r2, uint32_t& r3, uint32_t addr) {
    asm volatile("ldmatrix.sync.aligned.m8n8.x4.shared.b16 {%0,%1,%2,%3}, [%4];"
                 : "=r"(r0), "=r"(r1), "=r"(r2), "=r"(r3) : "r"(addr));
}

__device__ __forceinline__ void mma16816(float* c, const uint32_t* a,
                                         uint32_t b0, uint32_t b1) {
    asm volatile(
        "mma.sync.aligned.m16n8k16.row.col.f32.bf16.bf16.f32 "
        "{%0,%1,%2,%3}, {%4,%5,%6,%7}, {%8,%9}, {%0,%1,%2,%3};"
        : "+f"(c[0]), "+f"(c[1]), "+f"(c[2]), "+f"(c[3])
        : "r"(a[0]), "r"(a[1]), "r"(a[2]), "r"(a[3]), "r"(b0), "r"(b1));
}

__device__ __forceinline__ uint32_t sw128(uint32_t off) {
    return off ^ ((off >> 3) & 0x70);
}

__device__ __forceinline__ float softplusf_(float v) {
    return v > 20.f ? v : log1pf(__expf(v));
}
__device__ __forceinline__ float gelu_tanh_(float v) {
    float u = 0.7978845608028654f * (v + 0.044715f * v * v * v);
    return 0.5f * v * (1.f + tanhf(u));
}

// ---------------------------------------------------------------------------
// Kernel 0: convert x -> bf16 (row-major and transposed)
// ---------------------------------------------------------------------------
__global__ __launch_bounds__(256) void k_cvt(const float* __restrict__ x) {
    __shared__ __nv_bfloat16 tile[32][34];
    const int b  = blockIdx.z;
    const int t0 = blockIdx.x * 32;
    const int d0 = blockIdx.y * 32;
    const int lx = threadIdx.x;   // 0..15
    const int ly = threadIdx.y;   // 0..15
    const float* X = x + (size_t)b * T_ * D_;

#pragma unroll
    for (int r = 0; r < 2; r++) {
        const int t = t0 + ly + r * 16;
        const int d = d0 + lx * 2;
        float2 v = *(const float2*)(X + (size_t)t * D_ + d);
        __nv_bfloat162 h = __floats2bfloat162_rn(v.x, v.y);
        *(uint32_t*)(g_Xh + (size_t)(b * T_ + t) * D_ + d) = *(uint32_t*)&h;
        tile[ly + r * 16][lx * 2 + 0] = h.x;
        tile[ly + r * 16][lx * 2 + 1] = h.y;
    }
    __syncthreads();
#pragma unroll
    for (int r = 0; r < 2; r++) {
        const int d  = d0 + ly + r * 16;
        const int tp = lx * 2;
        __nv_bfloat162 h;
        h.x = tile[tp + 0][ly + r * 16];
        h.y = tile[tp + 1][ly + r * 16];
        *(uint32_t*)(g_XhT + ((size_t)b * D_ + d) * T_ + t0 + tp) = *(uint32_t*)&h;
    }
}

// ---------------------------------------------------------------------------
// MMA over one K=64 chunk. CTA tile 64(m) x 128(n), 8 warps = 2m x 4n of 32x32.
// ---------------------------------------------------------------------------
__device__ __forceinline__ void mma_chunk(uint32_t sA, uint32_t sB,
                                          int warp_m, int warp_n, int lane,
                                          float c[2][4][4]) {
    const int rowsel = lane & 15;
    const int khalf  = (lane >> 4) * 16;
    // base addresses (kbyte folded in via XOR since kbyte < 128)
    const uint32_t a0 = sA + (warp_m * 32 + 0  + rowsel) * 128;
    const uint32_t a1 = sA + (warp_m * 32 + 16 + rowsel) * 128;
    const uint32_t b0a = sB + (warp_n * 32 + 0  + rowsel) * 128;
    const uint32_t b1a = sB + (warp_n * 32 + 16 + rowsel) * 128;
    const uint32_t xa0 = ((warp_m * 32 + 0  + rowsel) & 7) << 4;
    const uint32_t xa1 = ((warp_m * 32 + 16 + rowsel) & 7) << 4;
    const uint32_t xb0 = ((warp_n * 32 + 0  + rowsel) & 7) << 4;
    const uint32_t xb1 = ((warp_n * 32 + 16 + rowsel) & 7) << 4;
#pragma unroll
    for (int ks = 0; ks < 4; ks++) {
        const uint32_t kb = ks * 32 + khalf;
        uint32_t a[2][4];
        ldmx4(a[0][0], a[0][1], a[0][2], a[0][3], a0 + (kb ^ xa0));
        ldmx4(a[1][0], a[1][1], a[1][2], a[1][3], a1 + (kb ^ xa1));
        uint32_t b[4][2];
        {
            uint32_t r0, r1, r2, r3;
            ldmx4(r0, r1, r2, r3, b0a + (kb ^ xb0));
            b[0][0] = r0; b[1][0] = r1; b[0][1] = r2; b[1][1] = r3;
            ldmx4(r0, r1, r2, r3, b1a + (kb ^ xb1));
            b[2][0] = r0; b[3][0] = r1; b[2][1] = r2; b[3][1] = r3;
        }
#pragma unroll
        for (int mi = 0; mi < 2; mi++)
#pragma unroll
            for (int ni = 0; ni < 4; ni++)
                mma16816(c[mi][ni], a[mi], b[ni][0], b[ni][1]);
    }
}

// Stage loads: A = 64 rows x 128B (2 cp16/thread), B = 128 rows x 128B (4/thread)
__device__ __forceinline__ void load_tileA(uint32_t sdst,
                                           const __nv_bfloat16* __restrict__ src,
                                           size_t row_stride, int tid) {
    const int row = tid >> 2;
    const int cb  = (tid & 3) * 2;
    const __nv_bfloat16* g = src + (size_t)row * row_stride + cb * 8;
#pragma unroll
    for (int c = 0; c < 2; c++)
        cp16(sdst + sw128(row * 128 + (cb + c) * 16), g + c * 8);
}
__device__ __forceinline__ void load_tileB(uint32_t sdst,
                                           const __nv_bfloat16* __restrict__ src,
                                           size_t row_stride, int tid) {
    const int row = tid >> 1;
    const int cb  = (tid & 1) * 4;
    const __nv_bfloat16* g = src + (size_t)row * row_stride + cb * 8;
#pragma unroll
    for (int c = 0; c < 4; c++)
        cp16(sdst + sw128(row * 128 + (cb + c) * 16), g + c * 8);
}

// ---------------------------------------------------------------------------
// Kernel 1: S = exp(SCALE * X X^T) bf16, strict causal.
// CTA = 64 query rows x 128 key cols. Early-exit fully-masked tiles.
// ---------------------------------------------------------------------------
__global__ __launch_bounds__(256, 3) void k_qk_mma() {
    const int sb  = blockIdx.x;        // key 128-block
    const int tb6 = blockIdx.y;        // query 64-block
    const int b   = blockIdx.z;
    if (sb > (tb6 >> 1)) return;       // tile entirely s >= t: masked

    extern __shared__ __align__(1024) char smem[];
    const uint32_t sbase = smem_u32(smem);
    const int tid = threadIdx.x, lane = tid & 31, wid = tid >> 5;
    const int warp_m = wid & 1, warp_n = wid >> 1;

    const __nv_bfloat16* A0 = g_Xh + (size_t)(b * T_ + tb6 * 64)  * D_;
    const __nv_bfloat16* B0 = g_Xh + (size_t)(b * T_ + sb * 128)  * D_;

    float c[2][4][4];
#pragma unroll
    for (int mi = 0; mi < 2; mi++)
#pragma unroll
        for (int ni = 0; ni < 4; ni++)
#pragma unroll
            for (int k = 0; k < 4; k++) c[mi][ni][k] = 0.f;

    const int nIter = D_ / 64;   // 16
#pragma unroll
    for (int s = 0; s < NSTAGE - 1; s++) {
        const uint32_t st = sbase + s * STAGE_BYTES;
        load_tileA(st,           A0 + s * 64, D_, tid);
        load_tileB(st + A_BYTES, B0 + s * 64, D_, tid);
        CP_COMMIT();
    }

    for (int it = 0; it < nIter; ++it) {
        if (it + NSTAGE - 1 < nIter) CP_WAIT(NSTAGE - 2); else CP_WAIT(0);
        __syncthreads();
        if (it + NSTAGE - 1 < nIter) {
            const int ld = it + NSTAGE - 1;
            const uint32_t stb = sbase + (ld % NSTAGE) * STAGE_BYTES;
            load_tileA(stb,           A0 + ld * 64, D_, tid);
            load_tileB(stb + A_BYTES, B0 + ld * 64, D_, tid);
            CP_COMMIT();
        }
        const uint32_t st = sbase + (it % NSTAGE) * STAGE_BYTES;
        mma_chunk(st, st + A_BYTES, warp_m, warp_n, lane, c);
    }

    // epilogue: exp + strict mask, bf16 store
    const int quad = lane >> 2, qid = lane & 3;
#pragma unroll
    for (int mi = 0; mi < 2; mi++) {
#pragma unroll
        for (int ni = 0; ni < 4; ni++) {
            const int col = warp_n * 32 + ni * 8 + qid * 2;
            const int s0  = sb * 128 + col;
#pragma unroll
            for (int h = 0; h < 2; h++) {
                const int row = warp_m * 32 + mi * 16 + quad + h * 8;
                const int t   = tb6 * 64 + row;
                float v0 = (s0 + 0 < t) ? __expf(c[mi][ni][2 * h + 0] * SCALE_) : 0.f;
                float v1 = (s0 + 1 < t) ? __expf(c[mi][ni][2 * h + 1] * SCALE_) : 0.f;
                __nv_bfloat162 hv = __floats2bfloat162_rn(v0, v1);
                *(uint32_t*)(g_Sh + ((size_t)(b * T_ + t)) * T_ + s0) = *(uint32_t*)&hv;
            }
        }
    }
}

// ---------------------------------------------------------------------------
// Kernel 2: denominators. One warp per (b,t) row (masked entries are zeros).
// ---------------------------------------------------------------------------
__global__ __launch_bounds__(256) void k_denom() {
    const int warp = (blockIdx.x * 256 + threadIdx.x) >> 5;
    const int lane = threadIdx.x & 31;
    if (warp >= B_ * T_) return;
    const int b = warp / T_, t = warp % T_;
    const int Kmax = ((t >> 7) + 1) << 7;
    const __nv_bfloat162* row2 =
        (const __nv_bfloat162*)(g_Sh + ((size_t)b * T_ + t) * T_);
    float s = 0.f;
    const int np = Kmax >> 1;
    for (int j = lane; j < np; j += 32) {
        float2 f = __bfloat1622float2(row2[j]);
        s += f.x + f.y;
    }
#pragma unroll
    for (int o = 16; o; o >>= 1) s += __shfl_down_sync(0xFFFFFFFFu, s, o);
    if (lane == 0) g_den[warp] = s;
}

// ---------------------------------------------------------------------------
// Kernel 3: context = (S @ X) / den. CTA = 64 t-rows x 128 d-cols. Heavy-first.
// ---------------------------------------------------------------------------
__global__ __launch_bounds__(256, 3) void k_av_mma() {
    const int nb  = blockIdx.x;
    const int tb6 = (int)gridDim.y - 1 - (int)blockIdx.y;   // heavy-first
    const int b   = blockIdx.z;

    extern __shared__ __align__(1024) char smem[];
    const uint32_t sbase = smem_u32(smem);
    const int tid = threadIdx.x, lane = tid & 31, wid = tid >> 5;
    const int warp_m = wid & 1, warp_n = wid >> 1;

    const __nv_bfloat16* A0 = g_Sh  + (size_t)(b * T_ + tb6 * 64) * T_;
    const __nv_bfloat16* B0 = g_XhT + ((size_t)b * D_ + nb * 128) * T_;

    float c[2][4][4];
#pragma unroll
    for (int mi = 0; mi < 2; mi++)
#pragma unroll
        for (int ni = 0; ni < 4; ni++)
#pragma unroll
            for (int k = 0; k < 4; k++) c[mi][ni][k] = 0.f;

    const int nIter = ((tb6 >> 1) + 1) * 2;   // computed S width in 64-chunks
#pragma unroll
    for (int s = 0; s < NSTAGE - 1; s++) {
        if (s < nIter) {
            const uint32_t st = sbase + s * STAGE_BYTES;
            load_tileA(st,           A0 + s * 64, T_, tid);
            load_tileB(st + A_BYTES, B0 + s * 64, T_, tid);
            CP_COMMIT();
        }
    }

    for (int it = 0; it < nIter; ++it) {
        if (it + NSTAGE - 1 < nIter) CP_WAIT(NSTAGE - 2); else CP_WAIT(0);
        __syncthreads();
        if (it + NSTAGE - 1 < nIter) {
            const int ld = it + NSTAGE - 1;
            const uint32_t stb = sbase + (ld % NSTAGE) * STAGE_BYTES;
            load_tileA(stb,           A0 + ld * 64, T_, tid);
            load_tileB(stb + A_BYTES, B0 + ld * 64, T_, tid);
            CP_COMMIT();
        }
        const uint32_t st = sbase + (it % NSTAGE) * STAGE_BYTES;
        mma_chunk(st, st + A_BYTES, warp_m, warp_n, lane, c);
    }

    // epilogue: divide by denom, fp32 store
    const int quad = lane >> 2, qid = lane & 3;
#pragma unroll
    for (int mi = 0; mi < 2; mi++) {
#pragma unroll
        for (int h = 0; h < 2; h++) {
            const int row = warp_m * 32 + mi * 16 + quad + h * 8;
            const int t   = tb6 * 64 + row;
            const float den = g_den[b * T_ + t];
            const float inv = den > 0.f ? 1.f / den : 0.f;
            float* crow = g_C + ((size_t)(b * T_ + t)) * D_ + nb * 128;
#pragma unroll
            for (int ni = 0; ni < 4; ni++) {
                const int col = warp_n * 32 + ni * 8 + qid * 2;
                float2 v;
                v.x = c[mi][ni][2 * h + 0] * inv;
                v.y = c[mi][ni][2 * h + 1] * inv;
                *(float2*)(crow + col) = v;
            }
        }
    }
}

// ---------------------------------------------------------------------------
// Kernel 4: cosine / novelty / gate / tanh-GELU. One CTA per (b,t) row.
// ---------------------------------------------------------------------------
__global__ __launch_bounds__(256) void k_epi(const float* __restrict__ x,
                                             const float* __restrict__ p_la,
                                             const float* __restrict__ p_ls,
                                             float* __restrict__ out) {
    const int row = blockIdx.x;
    const int tid = threadIdx.x;
    const float4 xv = *((const float4*)x   + (size_t)row * 256 + tid);
    const float4 cv = *((const float4*)g_C + (size_t)row * 256 + tid);

    float xx = xv.x * xv.x + xv.y * xv.y + xv.z * xv.z + xv.w * xv.w;
    float cc = cv.x * cv.x + cv.y * cv.y + cv.z * cv.z + cv.w * cv.w;
    float xc = xv.x * cv.x + xv.y * cv.y + xv.z * cv.z + xv.w * cv.w;

#pragma unroll
    for (int o = 16; o; o >>= 1) {
        xx += __shfl_down_sync(0xFFFFFFFFu, xx, o);
        cc += __shfl_down_sync(0xFFFFFFFFu, cc, o);
        xc += __shfl_down_sync(0xFFFFFFFFu, xc, o);
    }

    __shared__ float s_xx[8], s_cc[8], s_xc[8];
    __shared__ float s_gate;
    const int lane = tid & 31, w = tid >> 5;
    if (lane == 0) { s_xx[w] = xx; s_cc[w] = cc; s_xc[w] = xc; }
    __syncthreads();
    if (tid == 0) {
        float fxx = 0.f, fcc = 0.f, fxc = 0.f;
#pragma unroll
        for (int k = 0; k < 8; k++) { fxx += s_xx[k]; fcc += s_cc[k]; fxc += s_xc[k]; }
        const float nx = fmaxf(sqrtf(fxx), 1e-12f);
        const float nc = fmaxf(sqrtf(fcc), 1e-12f);
        const float cosv = fxc / (nx * nc);
        const float nov  = fminf(fmaxf(1.f - cosv, 0.f), 2.f) * 0.5f;
        const float alpha = softplusf_(*p_la);
        const float sigma = softplusf_(*p_ls);
        s_gate = 1.f + alpha * tanhf(sigma * nov);
    }
    __syncthreads();
    const float g = s_gate;

    float4 o;
    o.x = gelu_tanh_(xv.x * g);
    o.y = gelu_tanh_(xv.y * g);
    o.z = gelu_tanh_(xv.z * g);
    o.w = gelu_tanh_(xv.w * g);
    *((float4*)out + (size_t)row * 256 + tid) = o;
}

// ---------------------------------------------------------------------------
extern "C" void kernel_launch(void* const* d_in, const int* in_sizes, int n_in,
                              void* d_out, int out_size) {
    const float* x  = (const float*)d_in[0];
    const float* la = (const float*)d_in[1];
    const float* ls = (const float*)d_in[2];
    float* out = (float*)d_out;

    const int smem_bytes = NSTAGE * STAGE_BYTES;   // 73728
    cudaFuncSetAttribute(k_qk_mma, cudaFuncAttributeMaxDynamicSharedMemorySize, smem_bytes);
    cudaFuncSetAttribute(k_av_mma, cudaFuncAttributeMaxDynamicSharedMemorySize, smem_bytes);

    dim3 gc(T_ / 32, D_ / 32, B_);
    k_cvt<<<gc, dim3(16, 16)>>>(x);

    dim3 g1(16, 32, B_);          // sb, tb6, b (early-exit upper tiles)
    k_qk_mma<<<g1, 256, smem_bytes>>>();

    k_denom<<<(B_ * T_) / 8, 256>>>();

    dim3 g3(8, 32, B_);           // nb, tb6 (reversed), b
    k_av_mma<<<g3, 256, smem_bytes>>>();

    k_epi<<<B_ * T_, 256>>>(x, la, ls, out);
}